// round 6
// baseline (speedup 1.0000x reference)
#include <cuda_runtime.h>
#include <cuda_bf16.h>

// HOG on GB300. ang = |atan2(gx, gy)| in [0,pi], bin = floor(ang*8/pi) in 0..8.
// Symmetric binning: t_k = |gy| - c_k*|gx|, c = {0.414.., 1, 2.414..}, q = (gy<=0):
//   upper (gy>0):  ang >= k*pi/8 (k=1,2,3)  <=>  t_{4-k} <= 0
//   lower (gy<=0): ang >= k*pi/8 (k=1..4) always; k=5,6,7 <=> t_{k-4} >= 0
//   ang == pi  <=>  gx==0 && gy<0.
// Accumulate prefix sums A0 (all), U1..U3 (upper), N (all lower), L5..L8 (lower);
// per-bin values by differences once per cell.
// Each 8x8 cell is split across 2 adjacent lanes (4 cols x 8 rows each);
// pair combined with shfl_xor(.,1). Row loads are unconditional (clamped row
// index) with rare uniform zero-fix for cy==0 / cy==63 instead of per-row branches.

__device__ __forceinline__ float fsqrt_approx(float v) {
    float r; asm("sqrt.approx.f32 %0, %1;" : "=f"(r) : "f"(v)); return r;
}

__global__ void __launch_bounds__(256) hog_kernel(const float* __restrict__ x,
                                                  float* __restrict__ out) {
    const int t  = blockIdx.x * 256 + threadIdx.x;
    const int h  = t & 1;            // half of the cell (cols 0-3 / 4-7)
    const int cx = (t >> 1) & 63;
    const int cy = (t >> 7) & 63;
    const int b  = t >> 13;
    const int C  = (cx << 3) + (h << 2);   // first owned column
    const int R  = cy << 3;
    const float* img = x + (size_t)b * (512 * 512);
    const bool cL = (C > 0);
    const bool cR = (C < 508);

    // rolling raw rows: cols C-1 .. C+4 (6 floats each)
    float rows[3][6];

#define LOAD_ROW(RI, rclamped)                                                 \
    {                                                                          \
        const float* _p = img + (rclamped) * 512 + C;                          \
        rows[RI][0] = cL ? _p[-1] : 0.f;                                       \
        float4 _v = *(const float4*)(_p);                                      \
        rows[RI][1] = _v.x; rows[RI][2] = _v.y;                                \
        rows[RI][3] = _v.z; rows[RI][4] = _v.w;                                \
        rows[RI][5] = cR ? _p[4] : 0.f;                                        \
    }

    float A0 = 0.f, U1 = 0.f, U2 = 0.f, U3 = 0.f, N = 0.f,
          L5 = 0.f, L6 = 0.f, L7 = 0.f, L8 = 0.f;

    // prologue: row R-1 (clamped; zeroed for cy==0) and row R
    LOAD_ROW(0, (R > 0 ? R - 1 : 0));
    if (cy == 0) {
#pragma unroll
        for (int j = 0; j < 6; j++) rows[0][j] = 0.f;
    }
    LOAD_ROW(1, R);

#pragma unroll
    for (int rr = 0; rr < 8; rr++) {
        const int ia = rr % 3;          // row R+rr-1
        const int ib = (rr + 1) % 3;    // row R+rr
        const int ic = (rr + 2) % 3;    // row R+rr+1
        // next row: only iteration 7 can go out of range (R+8 == 512 iff cy==63)
        if (rr < 7) {
            LOAD_ROW(ic, R + rr + 1);
        } else {
            LOAD_ROW(ic, (R + 8 < 512 ? R + 8 : 511));
            if (cy == 63) {
#pragma unroll
                for (int j = 0; j < 6; j++) rows[ic][j] = 0.f;
            }
        }

        // vertical separable passes: s = [1,2,1] smooth, d = [-1,0,1] diff
        float s[6], d[6];
#pragma unroll
        for (int j = 0; j < 6; j++) {
            s[j] = fmaf(2.f, rows[ib][j], rows[ia][j] + rows[ic][j]);
            d[j] = rows[ic][j] - rows[ia][j];
        }

#pragma unroll
        for (int i = 0; i < 4; i++) {
            // gx = s[col+1]-s[col-1]; gy = d[col-1]+2d[col]+d[col+1]
            const float gx = s[i + 2] - s[i];
            const float gy = fmaf(2.f, d[i + 1], d[i] + d[i + 2]);
            const float a  = fabsf(gx), u = fabsf(gy);
            const float mag = fsqrt_approx(fmaf(gx, gx, gy * gy));
            const float t1 = fmaf(-0.4142135623730951f, a, u);
            const float t2 = u - a;
            const float t3 = fmaf(-2.414213562373095f, a, u);
            const bool  q  = (gy <= 0.f);
            A0 += mag;
            if (q)               N  += mag;   // lower half: ang >= 4*pi/8 always
            if (!q && t3 <= 0.f) U1 += mag;   // ang >= 1*pi/8 (upper)
            if (!q && t2 <= 0.f) U2 += mag;   // ang >= 2*pi/8
            if (!q && t1 <= 0.f) U3 += mag;   // ang >= 3*pi/8
            if (q && t1 >= 0.f)  L5 += mag;   // ang >= 5*pi/8
            if (q && t2 >= 0.f)  L6 += mag;   // ang >= 6*pi/8
            if (q && t3 >= 0.f)  L7 += mag;   // ang >= 7*pi/8
            if (q && gx == 0.f)  L8 += mag;   // ang == pi (mag==0 if gy==0 too)
        }
    }
#undef LOAD_ROW

    // combine the two half-cell lanes (partner = lane^1)
    A0 += __shfl_xor_sync(0xFFFFFFFFu, A0, 1);
    U1 += __shfl_xor_sync(0xFFFFFFFFu, U1, 1);
    U2 += __shfl_xor_sync(0xFFFFFFFFu, U2, 1);
    U3 += __shfl_xor_sync(0xFFFFFFFFu, U3, 1);
    N  += __shfl_xor_sync(0xFFFFFFFFu, N,  1);
    L5 += __shfl_xor_sync(0xFFFFFFFFu, L5, 1);
    L6 += __shfl_xor_sync(0xFFFFFFFFu, L6, 1);
    L7 += __shfl_xor_sync(0xFFFFFFFFu, L7, 1);
    L8 += __shfl_xor_sync(0xFFFFFFFFu, L8, 1);

    // bins from prefix differences; split the 9 stores across the lane pair
    float* o = out + (size_t)b * (9 * 4096) + (cy << 6) + cx;
    if (h == 0) {
        o[0 * 4096] = A0 - (U1 + N);
        o[1 * 4096] = U1 - U2;
        o[2 * 4096] = U2 - U3;
        o[3 * 4096] = U3;
        o[4 * 4096] = N - L5;
    } else {
        o[5 * 4096] = L5 - L6;
        o[6 * 4096] = L6 - L7;
        o[7 * 4096] = L7 - L8;
        o[8 * 4096] = L8;
    }
}

extern "C" void kernel_launch(void* const* d_in, const int* in_sizes, int n_in,
                              void* d_out, int out_size) {
    const float* x = (const float*)d_in[0];
    float* out = (float*)d_out;
    // 64 batches * 64*64 cells * 2 half-cells = 524288 threads
    hog_kernel<<<2048, 256>>>(x, out);
}

// round 7
// speedup vs baseline: 1.6386x; 1.6386x over previous
#include <cuda_runtime.h>
#include <cuda_bf16.h>

// HOG: gx,gy = sobel (cross-correlation, zero pad), mag = sqrt(gx^2+gy^2),
// ang = |atan2(gx, gy)| in [0, pi], bin = floor(ang*8/pi) in 0..8,
// out[b][bin][cy][cx] = sum of mag over the 8x8 cell.
//
// Binning without atan2: ang >= k*pi/8  <=>  cot(k*pi/8)*|gx| - gy >= 0.
// Predicates monotone in k -> accumulate prefix sums A[k], per-bin = A[k]-A[k+1].
// Bin 8 (ang == pi) iff gx==0 && gy<0.
//
// Each 8x8 cell split across 2 adjacent lanes (4 cols x 8 rows each) to cut
// register pressure; pair combined with shfl_xor(.,1).
// R7: exact R2 code + __launch_bounds__(256,5) to pin regs <= 51 and
// guarantee 5 CTAs/SM (R2 measured regs=50, occ only 42.7%).

__device__ __forceinline__ float fsqrt_approx(float v) {
    float r;
    asm("sqrt.approx.f32 %0, %1;" : "=f"(r) : "f"(v));
    return r;
}

__global__ void __launch_bounds__(256, 5) hog_kernel(const float* __restrict__ x,
                                                     float* __restrict__ out) {
    const int t  = blockIdx.x * 256 + threadIdx.x;
    const int h  = t & 1;            // which half of the cell (cols 0-3 / 4-7)
    const int cx = (t >> 1) & 63;
    const int cy = (t >> 7) & 63;
    const int b  = t >> 13;
    const int C  = (cx << 3) + (h << 2);   // first owned column
    const int R  = cy << 3;
    const float* img = x + (size_t)b * (512 * 512);
    const bool cL = (C > 0);
    const bool cR = (C < 508);

    // rolling raw rows: cols C-1 .. C+4 (6 floats each)
    float rows[3][6];

#define LOAD_ROW(RI, rexpr)                                                    \
    {                                                                          \
        const int _r = (rexpr);                                                \
        if ((unsigned)_r < 512u) {                                             \
            const float* _p = img + _r * 512 + C;                              \
            rows[RI][0] = cL ? _p[-1] : 0.f;                                   \
            float4 _v = *(const float4*)(_p);                                  \
            rows[RI][1] = _v.x; rows[RI][2] = _v.y;                            \
            rows[RI][3] = _v.z; rows[RI][4] = _v.w;                            \
            rows[RI][5] = cR ? _p[4] : 0.f;                                    \
        } else {                                                               \
            _Pragma("unroll")                                                  \
            for (int _j = 0; _j < 6; _j++) rows[RI][_j] = 0.f;                 \
        }                                                                      \
    }

    // Prefix accumulators: A0 = sum(mag); Ak = sum(mag | ang >= k*pi/8)
    float A0 = 0.f, A1 = 0.f, A2 = 0.f, A3 = 0.f, A4 = 0.f,
          A5 = 0.f, A6 = 0.f, A7 = 0.f, A8 = 0.f;

    LOAD_ROW(0, R - 1);
    LOAD_ROW(1, R);

#pragma unroll
    for (int rr = 0; rr < 8; rr++) {
        const int ia = rr % 3;          // row R+rr-1
        const int ib = (rr + 1) % 3;    // row R+rr
        const int ic = (rr + 2) % 3;    // row R+rr+1
        LOAD_ROW(ic, R + rr + 1);

        // vertical separable passes: s = [1,2,1] smooth, d = [-1,0,1] diff
        float s[6], d[6];
#pragma unroll
        for (int j = 0; j < 6; j++) {
            s[j] = fmaf(2.f, rows[ib][j], rows[ia][j] + rows[ic][j]);
            d[j] = rows[ic][j] - rows[ia][j];
        }

#pragma unroll
        for (int i = 0; i < 4; i++) {
            // gx = s[col+1]-s[col-1]; gy = d[col-1]+2d[col]+d[col+1]
            float gx  = s[i + 2] - s[i];
            float gy  = fmaf(2.f, d[i + 1], d[i] + d[i + 2]);
            float a   = fabsf(gx);
            float mag = fsqrt_approx(fmaf(gx, gx, gy * gy));
            A0 += mag;
            // cot(k*pi/8) for k=1..7: 2.41421, 1, 0.41421, 0, -0.41421, -1, -2.41421
            if (fmaf(a,  2.414213562373095f, -gy) >= 0.f)  A1 += mag;
            if (a - gy                            >= 0.f)  A2 += mag;
            if (fmaf(a,  0.4142135623730951f, -gy) >= 0.f) A3 += mag;
            if (gy                                <= 0.f)  A4 += mag;
            if (fmaf(a, -0.4142135623730951f, -gy) >= 0.f) A5 += mag;
            if (a + gy                            <= 0.f)  A6 += mag;
            if (fmaf(a, -2.414213562373095f, -gy) >= 0.f)  A7 += mag;
            if (gx == 0.f && gy < 0.f)                     A8 += mag;  // ang == pi
        }
    }
#undef LOAD_ROW

    // combine the two half-cell lanes (partner differs in lane bit 0)
    A0 += __shfl_xor_sync(0xFFFFFFFFu, A0, 1);
    A1 += __shfl_xor_sync(0xFFFFFFFFu, A1, 1);
    A2 += __shfl_xor_sync(0xFFFFFFFFu, A2, 1);
    A3 += __shfl_xor_sync(0xFFFFFFFFu, A3, 1);
    A4 += __shfl_xor_sync(0xFFFFFFFFu, A4, 1);
    A5 += __shfl_xor_sync(0xFFFFFFFFu, A5, 1);
    A6 += __shfl_xor_sync(0xFFFFFFFFu, A6, 1);
    A7 += __shfl_xor_sync(0xFFFFFFFFu, A7, 1);
    A8 += __shfl_xor_sync(0xFFFFFFFFu, A8, 1);

    // out[b][k][cy][cx], per-bin value = A[k] - A[k+1]; split writes across pair
    float* o = out + (size_t)b * (9 * 4096) + (cy << 6) + cx;
    if (h == 0) {
        o[0 * 4096] = A0 - A1;
        o[1 * 4096] = A1 - A2;
        o[2 * 4096] = A2 - A3;
        o[3 * 4096] = A3 - A4;
        o[4 * 4096] = A4 - A5;
    } else {
        o[5 * 4096] = A5 - A6;
        o[6 * 4096] = A6 - A7;
        o[7 * 4096] = A7 - A8;
        o[8 * 4096] = A8;
    }
}

extern "C" void kernel_launch(void* const* d_in, const int* in_sizes, int n_in,
                              void* d_out, int out_size) {
    const float* x = (const float*)d_in[0];
    float* out = (float*)d_out;
    // 64 batches * 64*64 cells * 2 half-cells = 524288 threads
    hog_kernel<<<2048, 256>>>(x, out);
}

// round 8
// speedup vs baseline: 1.7497x; 1.0678x over previous
#include <cuda_runtime.h>
#include <cuda_bf16.h>

// HOG: gx,gy = sobel (true conv w/ zero pad), mag = sqrt(gx^2+gy^2),
// ang = |atan2(gx, gy)| in [0, pi], bin = floor(ang*8/pi) in 0..8,
// out[b][bin][cy][cx] = sum of mag over the 8x8 cell.
//
// Binning without atan2: ang >= k*pi/8  <=>  cot(k*pi/8)*|gx| - gy >= 0.
// Predicates monotone in k -> prefix sums A[k], per-bin = A[k]-A[k+1].
// Bin 8 (ang == pi) iff gx==0 && gy<0.
//
// Each 8x8 cell split across 2 adjacent lanes (4 cols x 8 rows each);
// pair combined with shfl_xor(.,1).
// R8: separable conv transposed — horizontal passes (hd, hs) computed once per
// RAW row and reused by 3 output rows (amortizes the expensive pass); compare
// fusion (a>=gy, gy<=-a) removes 2 FADDs/px.

__device__ __forceinline__ float fsqrt_approx(float v) {
    float r;
    asm("sqrt.approx.f32 %0, %1;" : "=f"(r) : "f"(v));
    return r;
}

__global__ void __launch_bounds__(256) hog_kernel(const float* __restrict__ x,
                                                  float* __restrict__ out) {
    const int t  = blockIdx.x * 256 + threadIdx.x;
    const int h  = t & 1;            // which half of the cell (cols 0-3 / 4-7)
    const int cx = (t >> 1) & 63;
    const int cy = (t >> 7) & 63;
    const int b  = t >> 13;
    const int C  = (cx << 3) + (h << 2);   // first owned column
    const int R  = cy << 3;
    const float* img = x + (size_t)b * (512 * 512);
    const bool cL = (C > 0);
    const bool cR = (C < 508);

    // rolling horizontal passes for 3 raw rows:
    // hd[i] = r[C+i+1] - r[C+i-1]   (right - left)
    // hs[i] = r[C+i-1] + 2 r[C+i] + r[C+i+1]
    float hd[3][4], hs[3][4];

#define LOAD_HPASS(RI, rexpr)                                                  \
    {                                                                          \
        const int _r = (rexpr);                                                \
        if ((unsigned)_r < 512u) {                                             \
            const float* _p = img + _r * 512 + C;                              \
            float _eL = cL ? _p[-1] : 0.f;                                     \
            float4 _v = *(const float4*)(_p);                                  \
            float _eR = cR ? _p[4] : 0.f;                                      \
            hd[RI][0] = _v.y - _eL;                                            \
            hd[RI][1] = _v.z - _v.x;                                           \
            hd[RI][2] = _v.w - _v.y;                                           \
            hd[RI][3] = _eR - _v.z;                                            \
            hs[RI][0] = fmaf(2.f, _v.x, _eL + _v.y);                           \
            hs[RI][1] = fmaf(2.f, _v.y, _v.x + _v.z);                          \
            hs[RI][2] = fmaf(2.f, _v.z, _v.y + _v.w);                          \
            hs[RI][3] = fmaf(2.f, _v.w, _v.z + _eR);                           \
        } else {                                                               \
            _Pragma("unroll")                                                  \
            for (int _j = 0; _j < 4; _j++) { hd[RI][_j] = 0.f; hs[RI][_j] = 0.f; } \
        }                                                                      \
    }

    // Prefix accumulators: A0 = sum(mag); Ak = sum(mag | ang >= k*pi/8)
    float A0 = 0.f, A1 = 0.f, A2 = 0.f, A3 = 0.f, A4 = 0.f,
          A5 = 0.f, A6 = 0.f, A7 = 0.f, A8 = 0.f;

    LOAD_HPASS(0, R - 1);
    LOAD_HPASS(1, R);

#pragma unroll
    for (int rr = 0; rr < 8; rr++) {
        const int ia = rr % 3;          // row R+rr-1 (top)
        const int ib = (rr + 1) % 3;    // row R+rr   (mid)
        const int ic = (rr + 2) % 3;    // row R+rr+1 (bottom)
        LOAD_HPASS(ic, R + rr + 1);

#pragma unroll
        for (int i = 0; i < 4; i++) {
            // gx = (right-left) smoothed vertically; gy = (bottom-top) smoothed horizontally
            const float gx = fmaf(2.f, hd[ib][i], hd[ia][i] + hd[ic][i]);
            const float gy = hs[ic][i] - hs[ia][i];
            const float a  = fabsf(gx);
            const float mag = fsqrt_approx(fmaf(gx, gx, gy * gy));
            A0 += mag;
            // cot(k*pi/8) for k=1..7: 2.41421, 1, 0.41421, 0, -0.41421, -1, -2.41421
            if (fmaf(a,  2.414213562373095f, -gy) >= 0.f)  A1 += mag;
            if (a >= gy)                                   A2 += mag;
            if (fmaf(a,  0.4142135623730951f, -gy) >= 0.f) A3 += mag;
            if (gy <= 0.f)                                 A4 += mag;
            if (fmaf(a, -0.4142135623730951f, -gy) >= 0.f) A5 += mag;
            if (gy <= -a)                                  A6 += mag;
            if (fmaf(a, -2.414213562373095f, -gy) >= 0.f)  A7 += mag;
            if (gx == 0.f && gy < 0.f)                     A8 += mag;  // ang == pi
        }
    }
#undef LOAD_HPASS

    // combine the two half-cell lanes (partner differs in lane bit 0)
    A0 += __shfl_xor_sync(0xFFFFFFFFu, A0, 1);
    A1 += __shfl_xor_sync(0xFFFFFFFFu, A1, 1);
    A2 += __shfl_xor_sync(0xFFFFFFFFu, A2, 1);
    A3 += __shfl_xor_sync(0xFFFFFFFFu, A3, 1);
    A4 += __shfl_xor_sync(0xFFFFFFFFu, A4, 1);
    A5 += __shfl_xor_sync(0xFFFFFFFFu, A5, 1);
    A6 += __shfl_xor_sync(0xFFFFFFFFu, A6, 1);
    A7 += __shfl_xor_sync(0xFFFFFFFFu, A7, 1);
    A8 += __shfl_xor_sync(0xFFFFFFFFu, A8, 1);

    // out[b][k][cy][cx], per-bin value = A[k] - A[k+1]; split writes across pair
    float* o = out + (size_t)b * (9 * 4096) + (cy << 6) + cx;
    if (h == 0) {
        o[0 * 4096] = A0 - A1;
        o[1 * 4096] = A1 - A2;
        o[2 * 4096] = A2 - A3;
        o[3 * 4096] = A3 - A4;
        o[4 * 4096] = A4 - A5;
    } else {
        o[5 * 4096] = A5 - A6;
        o[6 * 4096] = A6 - A7;
        o[7 * 4096] = A7 - A8;
        o[8 * 4096] = A8;
    }
}

extern "C" void kernel_launch(void* const* d_in, const int* in_sizes, int n_in,
                              void* d_out, int out_size) {
    const float* x = (const float*)d_in[0];
    float* out = (float*)d_out;
    // 64 batches * 64*64 cells * 2 half-cells = 524288 threads
    hog_kernel<<<2048, 256>>>(x, out);
}

// round 9
// speedup vs baseline: 1.7981x; 1.0276x over previous
#include <cuda_runtime.h>
#include <cuda_bf16.h>

// HOG: gx,gy = sobel cross-correlation (zero pad), mag = sqrt(gx^2+gy^2),
// ang = |atan2(gx, gy)| in [0, pi], bin = floor(ang*8/pi) in 0..8,
// out[b][bin][cy][cx] = sum of mag over the 8x8 cell.
//
// Binning without atan2: ang >= k*pi/8  <=>  cot(k*pi/8)*|gx| - gy >= 0.
// Predicates monotone in k -> prefix sums A[k], per-bin = A[k]-A[k+1].
// Bin 8 (ang == pi) iff gx==0 && gy<0.
//
// R9: 1 thread = full 8x8 cell (no lane split, no shuffles). Transposed
// separable conv: horizontal passes hd/hs computed once per RAW row, reused by
// 3 output rows. Bounds checks only on rows R-1 and R+8 (rows R..R+7 are
// always in range), removing 8 of 10 guard blocks per thread.

__device__ __forceinline__ float fsqrt_approx(float v) {
    float r;
    asm("sqrt.approx.f32 %0, %1;" : "=f"(r) : "f"(v));
    return r;
}

__global__ void __launch_bounds__(256) hog_kernel(const float* __restrict__ x,
                                                  float* __restrict__ out) {
    const int t  = blockIdx.x * 256 + threadIdx.x;
    const int cx = t & 63;
    const int cy = (t >> 6) & 63;
    const int b  = t >> 12;
    const int C  = cx << 3;
    const int R  = cy << 3;
    const float* img = x + (size_t)b * (512 * 512);
    const bool cL = (cx > 0);
    const bool cR = (cx < 63);

    // rolling horizontal passes for 3 raw rows over 8 columns:
    // hd[i] = r[C+i+1] - r[C+i-1],  hs[i] = r[C+i-1] + 2 r[C+i] + r[C+i+1]
    float hd[3][8], hs[3][8];

    // unchecked row load + horizontal pass (row index guaranteed in range)
#define LOAD_H(RI, rrow)                                                       \
    {                                                                          \
        const float* _p = img + (rrow) * 512 + C;                              \
        const float _eL = cL ? _p[-1] : 0.f;                                   \
        const float4 _v1 = *(const float4*)(_p);                               \
        const float4 _v2 = *(const float4*)(_p + 4);                           \
        const float _eR = cR ? _p[8] : 0.f;                                    \
        hd[RI][0] = _v1.y - _eL;                                               \
        hd[RI][1] = _v1.z - _v1.x;                                             \
        hd[RI][2] = _v1.w - _v1.y;                                             \
        hd[RI][3] = _v2.x - _v1.z;                                             \
        hd[RI][4] = _v2.y - _v1.w;                                             \
        hd[RI][5] = _v2.z - _v2.x;                                             \
        hd[RI][6] = _v2.w - _v2.y;                                             \
        hd[RI][7] = _eR - _v2.z;                                               \
        hs[RI][0] = fmaf(2.f, _v1.x, _eL + _v1.y);                             \
        hs[RI][1] = fmaf(2.f, _v1.y, _v1.x + _v1.z);                           \
        hs[RI][2] = fmaf(2.f, _v1.z, _v1.y + _v1.w);                           \
        hs[RI][3] = fmaf(2.f, _v1.w, _v1.z + _v2.x);                           \
        hs[RI][4] = fmaf(2.f, _v2.x, _v1.w + _v2.y);                           \
        hs[RI][5] = fmaf(2.f, _v2.y, _v2.x + _v2.z);                           \
        hs[RI][6] = fmaf(2.f, _v2.z, _v2.y + _v2.w);                           \
        hs[RI][7] = fmaf(2.f, _v2.w, _v2.z + _eR);                             \
    }

#define ZERO_H(RI)                                                             \
    {                                                                          \
        _Pragma("unroll")                                                      \
        for (int _j = 0; _j < 8; _j++) { hd[RI][_j] = 0.f; hs[RI][_j] = 0.f; } \
    }

    // Prefix accumulators: A0 = sum(mag); Ak = sum(mag | ang >= k*pi/8)
    float A0 = 0.f, A1 = 0.f, A2 = 0.f, A3 = 0.f, A4 = 0.f,
          A5 = 0.f, A6 = 0.f, A7 = 0.f, A8 = 0.f;

    // prologue: row R-1 (guarded — OOB only for cy==0), row R (always valid)
    if (cy > 0) { LOAD_H(0, R - 1); } else { ZERO_H(0); }
    LOAD_H(1, R);

#pragma unroll
    for (int rr = 0; rr < 8; rr++) {
        const int ia = rr % 3;          // row R+rr-1 (top)
        const int ib = (rr + 1) % 3;    // row R+rr   (mid)
        const int ic = (rr + 2) % 3;    // row R+rr+1 (bottom)
        if (rr < 7) {
            LOAD_H(ic, R + rr + 1);     // rows R+1..R+7: always in [0,511]
        } else {
            if (cy < 63) { LOAD_H(ic, R + 8); } else { ZERO_H(ic); }
        }

#pragma unroll
        for (int i = 0; i < 8; i++) {
            // gx = (right-left) smoothed vertically; gy = (bottom-top) smoothed horizontally
            const float gx = fmaf(2.f, hd[ib][i], hd[ia][i] + hd[ic][i]);
            const float gy = hs[ic][i] - hs[ia][i];
            const float a  = fabsf(gx);
            const float mag = fsqrt_approx(fmaf(gx, gx, gy * gy));
            A0 += mag;
            // cot(k*pi/8) for k=1..7: 2.41421, 1, 0.41421, 0, -0.41421, -1, -2.41421
            if (fmaf(a,  2.414213562373095f, -gy) >= 0.f)  A1 += mag;
            if (a >= gy)                                   A2 += mag;
            if (fmaf(a,  0.4142135623730951f, -gy) >= 0.f) A3 += mag;
            if (gy <= 0.f)                                 A4 += mag;
            if (fmaf(a, -0.4142135623730951f, -gy) >= 0.f) A5 += mag;
            if (gy <= -a)                                  A6 += mag;
            if (fmaf(a, -2.414213562373095f, -gy) >= 0.f)  A7 += mag;
            if (gx == 0.f && gy < 0.f)                     A8 += mag;  // ang == pi
        }
    }
#undef LOAD_H
#undef ZERO_H

    // out[b][k][cy][cx], per-bin value = A[k] - A[k+1]
    float* o = out + (size_t)b * (9 * 4096) + (cy << 6) + cx;
    o[0 * 4096] = A0 - A1;
    o[1 * 4096] = A1 - A2;
    o[2 * 4096] = A2 - A3;
    o[3 * 4096] = A3 - A4;
    o[4 * 4096] = A4 - A5;
    o[5 * 4096] = A5 - A6;
    o[6 * 4096] = A6 - A7;
    o[7 * 4096] = A7 - A8;
    o[8 * 4096] = A8;
}

extern "C" void kernel_launch(void* const* d_in, const int* in_sizes, int n_in,
                              void* d_out, int out_size) {
    const float* x = (const float*)d_in[0];
    float* out = (float*)d_out;
    // 64 batches * 64*64 cells = 262144 threads
    hog_kernel<<<1024, 256>>>(x, out);
}